// round 7
// baseline (speedup 1.0000x reference)
#include <cuda_runtime.h>
#include <math.h>

#define N_IMG   32
#define C_DIM   128
#define K_CL    64
#define S_TOT   12544
#define SC      128
#define NCHUNK  98          // S_TOT / SC
#define SPLIT   9
#define CPB     11          // ceil(NCHUNK / SPLIT)
#define THREADS 512
#define EPSV    1e-12f

#define XS_STRIDE 129       // odd -> conflict-free scalar row AND column access
#define LS_STRIDE 66        // even -> 8B-aligned k-pair LDS.64
#define WT_STRIDE 66

#define SMEM_FLOATS (2 * C_DIM * XS_STRIDE + SC * LS_STRIDE + C_DIM * WT_STRIDE)
#define SMEM_BYTES  (SMEM_FLOATS * 4)

typedef unsigned long long ull;

__device__ float g_vpart[(size_t)N_IMG * SPLIT * K_CL * C_DIM];
__device__ float g_apart[N_IMG * SPLIT * K_CL];
__device__ float g_gsum[N_IMG * 8];

__device__ __forceinline__ ull ffma2(ull a, ull b, ull c) {
    ull d;
    asm("fma.rn.f32x2 %0, %1, %2, %3;" : "=l"(d) : "l"(a), "l"(b), "l"(c));
    return d;
}
__device__ __forceinline__ ull pack2(float lo, float hi) {
    ull d;
    asm("mov.b64 %0, {%1, %2};" : "=l"(d) : "f"(lo), "f"(hi));
    return d;
}
__device__ __forceinline__ void unpack2(ull v, float& lo, float& hi) {
    asm("mov.b64 {%0, %1}, %2;" : "=f"(lo), "=f"(hi) : "l"(v));
}
__device__ __forceinline__ void cp4(float* dst, const float* src) {
    unsigned ds = (unsigned)__cvta_generic_to_shared(dst);
    asm volatile("cp.async.ca.shared.global [%0], [%1], 4;" :: "r"(ds), "l"(src));
}
__device__ __forceinline__ void cp_commit() {
    asm volatile("cp.async.commit_group;");
}
template<int N> __device__ __forceinline__ void cp_wait() {
    asm volatile("cp.async.wait_group %0;" :: "n"(N));
}

// Prefetch one 128x128 x-chunk into an Xs buffer (stride 129).
// Thread t owns s = t&127, c = 4r + (t>>7): coalesced gmem, conflict-free smem.
__device__ __forceinline__ void prefetch_chunk(float* Xbuf, const float* xb) {
    const int t  = threadIdx.x;
    const int s  = t & 127;
    const int ch = t >> 7;                 // 0..3
    float*       d = Xbuf + (size_t)ch * XS_STRIDE + s;
    const float* g = xb   + (size_t)ch * S_TOT     + s;
    #pragma unroll
    for (int r = 0; r < 32; r++) {
        cp4(d, g);
        d += 4 * XS_STRIDE;
        g += 4 * S_TOT;
    }
}

__global__ void __launch_bounds__(THREADS, 1)
netvlad_main(const float* __restrict__ x, const float* __restrict__ convw) {
    extern __shared__ float sm[];
    float* X0 = sm;                                  // [128][129]
    float* X1 = X0 + C_DIM * XS_STRIDE;              // [128][129]
    float* Ls = X1 + C_DIM * XS_STRIDE;              // [128 s][66]  logits/probs [s][k]
    float* Wt = Ls + SC * LS_STRIDE;                 // [128 c][66]  W transposed [c][k]

    const int n   = blockIdx.y;
    const int sp  = blockIdx.x;
    const int tid = threadIdx.x;
    const int w   = tid >> 5;
    const int l   = tid & 31;
    const int ko  = w & 7;        // k-octet: k-pairs 4*ko+j -> k = 8*ko+2*j
    const int hh  = w >> 3;       // s/c-half: pos = l + 32*(2*hh + i), i=0..1

    // ---- build Wt[c][k] from convw[k][c] (coalesced reads) ----
    for (int idx = tid; idx < K_CL * C_DIM; idx += THREADS) {
        int k = idx >> 7, c = idx & 127;
        Wt[c * WT_STRIDE + k] = convw[idx];
    }

    ull vacc[4][2];               // [j][i] vlad pairs {8ko+2j, +1} at c = l+32*(2hh+i)
    #pragma unroll
    for (int j = 0; j < 4; j++)
        #pragma unroll
        for (int i = 0; i < 2; i++) vacc[j][i] = 0ull;
    float asum = 0.f;

    const int chunk0 = sp * CPB;
    const int chunk1 = min(NCHUNK, chunk0 + CPB);
    const float* xb  = x + (size_t)n * C_DIM * S_TOT;

    prefetch_chunk(X0, xb + chunk0 * SC);
    cp_commit();
    __syncthreads();   // Wt ready

    for (int ch = chunk0; ch < chunk1; ch++) {
        float* Xb = ((ch - chunk0) & 1) ? X1 : X0;
        if (ch + 1 < chunk1) {
            float* Xn = ((ch + 1 - chunk0) & 1) ? X1 : X0;
            prefetch_chunk(Xn, xb + (ch + 1) * SC);
            cp_commit();
            cp_wait<1>();
        } else {
            cp_wait<0>();
        }
        __syncthreads();          // current buffer fully visible

        // ---- GEMM1: logit-pairs over k, vector over s (half per warp-group) ----
        {
            ull acc[4][2];
            #pragma unroll
            for (int j = 0; j < 4; j++)
                #pragma unroll
                for (int i = 0; i < 2; i++) acc[j][i] = 0ull;

            const float* xr = Xb + l + 64 * hh;
            const float* wr = Wt + 8 * ko;
            #pragma unroll 2
            for (int c = 0; c < C_DIM; c++) {
                ull wp[4];
                #pragma unroll
                for (int j = 0; j < 4; j++)
                    wp[j] = *(const ull*)(wr + 2 * j);      // broadcast pair
                ull xd[2];
                #pragma unroll
                for (int i = 0; i < 2; i++) {
                    float xv = xr[32 * i];
                    xd[i] = pack2(xv, xv);
                }
                #pragma unroll
                for (int j = 0; j < 4; j++)
                    #pragma unroll
                    for (int i = 0; i < 2; i++)
                        acc[j][i] = ffma2(wp[j], xd[i], acc[j][i]);
                xr += XS_STRIDE;
                wr += WT_STRIDE;
            }
            #pragma unroll
            for (int i = 0; i < 2; i++)
                #pragma unroll
                for (int j = 0; j < 4; j++)
                    *(ull*)(Ls + (l + 64 * hh + 32 * i) * LS_STRIDE + 8 * ko + 2 * j)
                        = acc[j][i];
        }
        __syncthreads();

        // ---- softmax over k for each pixel s (threads 0..127) ----
        if (tid < SC) {
            float* row = Ls + tid * LS_STRIDE;
            float m = -1e30f;
            #pragma unroll 8
            for (int k = 0; k < K_CL; k++) m = fmaxf(m, row[k]);
            float ssm = 0.f;
            #pragma unroll 8
            for (int k = 0; k < K_CL; k++) {
                float e = __expf(row[k] - m);
                row[k] = e;
                ssm += e;
            }
            float inv = 1.f / ssm;
            #pragma unroll 8
            for (int k = 0; k < K_CL; k++) row[k] *= inv;
        }
        __syncthreads();

        // ---- per-cluster assignment mass ----
        if (tid < K_CL) {
            float a = 0.f;
            #pragma unroll 8
            for (int s = 0; s < SC; s++) a += Ls[s * LS_STRIDE + tid];
            asum += a;
        }

        // ---- GEMM2: vlad-pairs over k, vector over c (half per warp-group) ----
        {
            const float* xr = Xb + (l + 64 * hh) * XS_STRIDE;
            const float* ar = Ls + 8 * ko;
            #pragma unroll 2
            for (int s = 0; s < SC; s++) {
                ull ap[4];
                #pragma unroll
                for (int j = 0; j < 4; j++)
                    ap[j] = *(const ull*)(ar + 2 * j);  // broadcast prob pair
                ull xd[2];
                #pragma unroll
                for (int i = 0; i < 2; i++) {
                    float xv = xr[(size_t)(32 * i) * XS_STRIDE];
                    xd[i] = pack2(xv, xv);
                }
                #pragma unroll
                for (int j = 0; j < 4; j++)
                    #pragma unroll
                    for (int i = 0; i < 2; i++)
                        vacc[j][i] = ffma2(ap[j], xd[i], vacc[j][i]);
                xr += 1;
                ar += LS_STRIDE;
            }
        }
        __syncthreads();   // protect Ls + prefetch target buffer
    }

    // ---- write deterministic partials ----
    float* vp = g_vpart + (size_t)(n * SPLIT + sp) * K_CL * C_DIM;
    #pragma unroll
    for (int j = 0; j < 4; j++) {
        const int k0 = 8 * ko + 2 * j;
        #pragma unroll
        for (int i = 0; i < 2; i++) {
            float lo, hi;
            unpack2(vacc[j][i], lo, hi);
            const int c = l + 64 * hh + 32 * i;
            vp[(k0 + 0) * C_DIM + c] = lo;
            vp[(k0 + 1) * C_DIM + c] = hi;
        }
    }
    if (tid < K_CL) g_apart[(n * SPLIT + sp) * K_CL + tid] = asum;
}

// reduce partials, subtract a*cent, intra-normalize, write out, per-group sumsq
__global__ void __launch_bounds__(256)
netvlad_reduce(const float* __restrict__ cent, float* __restrict__ out) {
    __shared__ float red[8];
    const int n   = blockIdx.y;
    const int kg  = blockIdx.x;          // 0..7
    const int tid = threadIdx.x;
    const int w   = tid >> 5, l = tid & 31;
    const int k   = kg * 8 + w;

    float as = 0.f;
    #pragma unroll
    for (int p = 0; p < SPLIT; p++) as += g_apart[(n * SPLIT + p) * K_CL + k];

    float4 v = make_float4(0.f, 0.f, 0.f, 0.f);
    #pragma unroll
    for (int p = 0; p < SPLIT; p++) {
        const float4* vp = (const float4*)(g_vpart +
            (size_t)(n * SPLIT + p) * K_CL * C_DIM + k * C_DIM);
        float4 t = vp[l];
        v.x += t.x; v.y += t.y; v.z += t.z; v.w += t.w;
    }
    float4 ct = ((const float4*)(cent + k * C_DIM))[l];
    v.x -= as * ct.x; v.y -= as * ct.y; v.z -= as * ct.z; v.w -= as * ct.w;

    float ss = v.x * v.x + v.y * v.y + v.z * v.z + v.w * v.w;
    #pragma unroll
    for (int o = 16; o; o >>= 1) ss += __shfl_xor_sync(0xffffffffu, ss, o);
    float inv = 1.f / fmaxf(sqrtf(ss), EPSV);
    v.x *= inv; v.y *= inv; v.z *= inv; v.w *= inv;
    ((float4*)(out + (size_t)n * K_CL * C_DIM + k * C_DIM))[l] = v;

    if (l == 0) red[w] = ss * inv * inv;   // sumsq of normalized row
    __syncthreads();
    if (tid == 0) {
        float g = 0.f;
        #pragma unroll
        for (int i = 0; i < 8; i++) g += red[i];
        g_gsum[n * 8 + kg] = g;
    }
}

__global__ void __launch_bounds__(256)
netvlad_scale(float* __restrict__ out) {
    const int n   = blockIdx.x;
    const int tid = threadIdx.x;
    float g = 0.f;
    #pragma unroll
    for (int i = 0; i < 8; i++) g += g_gsum[n * 8 + i];
    const float ginv = 1.f / fmaxf(sqrtf(g), EPSV);

    float4* ob = (float4*)(out + (size_t)n * K_CL * C_DIM);
    #pragma unroll
    for (int r = 0; r < 8; r++) {
        float4 v = ob[tid + 256 * r];
        v.x *= ginv; v.y *= ginv; v.z *= ginv; v.w *= ginv;
        ob[tid + 256 * r] = v;
    }
}

extern "C" void kernel_launch(void* const* d_in, const int* in_sizes, int n_in,
                              void* d_out, int out_size) {
    const float* x     = (const float*)d_in[0];
    const float* convw = (const float*)d_in[1];
    const float* cent  = (const float*)d_in[2];
    float*       out   = (float*)d_out;

    cudaFuncSetAttribute(netvlad_main,
                         cudaFuncAttributeMaxDynamicSharedMemorySize, SMEM_BYTES);
    netvlad_main<<<dim3(SPLIT, N_IMG), THREADS, SMEM_BYTES>>>(x, convw);
    netvlad_reduce<<<dim3(8, N_IMG), 256>>>(cent, out);
    netvlad_scale<<<N_IMG, 256>>>(out);
}

// round 11
// speedup vs baseline: 1.3428x; 1.3428x over previous
#include <cuda_runtime.h>
#include <cuda_bf16.h>
#include <cstdint>
#include <math.h>

#define N_IMG   32
#define C_DIM   128
#define K_CL    64
#define S_TOT   12544
#define SC      128
#define NCHUNK  98
#define SPLIT   9
#define CPB     11
#define THREADS 512
#define EPSV    1e-12f

// bf16 tile row stride: 136 bf16 = 272 bytes (272 mod 128 = 16 -> conflict-free ldmatrix)
#define TSTR    272
#define LSSTR   67          // fp32 words; odd -> conflict-free softmax row reads

// smem byte offsets
#define OFF_XCH 0
#define OFF_XCL (OFF_XCH + 128 * TSTR)      //  34816
#define OFF_WH  (OFF_XCL + 128 * TSTR)      //  69632
#define OFF_WL  (OFF_WH  +  64 * TSTR)      //  87040
#define OFF_PH  (OFF_WL  +  64 * TSTR)      // 104448
#define OFF_PL  (OFF_PH  +  64 * TSTR)      // 121856
#define OFF_LS  (OFF_PL  +  64 * TSTR)      // 139264
#define SMEM_BYTES (OFF_LS + 128 * LSSTR * 4)   // 173568

__device__ float g_vpart[(size_t)N_IMG * SPLIT * K_CL * C_DIM];
__device__ float g_apart[N_IMG * SPLIT * K_CL];
__device__ float g_gsum[N_IMG * 8];

// ---------------- PTX helpers ----------------
__device__ __forceinline__ void ldsm4(uint32_t* r, uint32_t a) {
    asm volatile("ldmatrix.sync.aligned.m8n8.x4.shared.b16 {%0,%1,%2,%3}, [%4];"
        : "=r"(r[0]), "=r"(r[1]), "=r"(r[2]), "=r"(r[3]) : "r"(a));
}
__device__ __forceinline__ void ldsm4t(uint32_t* r, uint32_t a) {
    asm volatile("ldmatrix.sync.aligned.m8n8.x4.trans.shared.b16 {%0,%1,%2,%3}, [%4];"
        : "=r"(r[0]), "=r"(r[1]), "=r"(r[2]), "=r"(r[3]) : "r"(a));
}
__device__ __forceinline__ void ldsm2(uint32_t* r, uint32_t a) {
    asm volatile("ldmatrix.sync.aligned.m8n8.x2.shared.b16 {%0,%1}, [%2];"
        : "=r"(r[0]), "=r"(r[1]) : "r"(a));
}
__device__ __forceinline__ void mma16816(float* d, const uint32_t* a, const uint32_t* b) {
    asm volatile("mma.sync.aligned.m16n8k16.row.col.f32.bf16.bf16.f32 "
        "{%0,%1,%2,%3}, {%4,%5,%6,%7}, {%8,%9}, {%0,%1,%2,%3};"
        : "+f"(d[0]), "+f"(d[1]), "+f"(d[2]), "+f"(d[3])
        : "r"(a[0]), "r"(a[1]), "r"(a[2]), "r"(a[3]), "r"(b[0]), "r"(b[1]));
}
__device__ __forceinline__ uint32_t pack_split(float a, float b, uint32_t& lo) {
    __nv_bfloat16 ah = __float2bfloat16_rn(a);
    __nv_bfloat16 bh = __float2bfloat16_rn(b);
    __nv_bfloat16 al = __float2bfloat16_rn(a - __bfloat162float(ah));
    __nv_bfloat16 bl = __float2bfloat16_rn(b - __bfloat162float(bh));
    lo = (uint32_t)__bfloat16_as_ushort(al) | ((uint32_t)__bfloat16_as_ushort(bl) << 16);
    return (uint32_t)__bfloat16_as_ushort(ah) | ((uint32_t)__bfloat16_as_ushort(bh) << 16);
}

__global__ void __launch_bounds__(THREADS, 1)
netvlad_main(const float* __restrict__ x, const float* __restrict__ convw) {
    extern __shared__ char smb[];
    const uint32_t sb = (uint32_t)__cvta_generic_to_shared(smb);

    const int n   = blockIdx.y;
    const int sp  = blockIdx.x;
    const int tid = threadIdx.x;
    const int w   = tid >> 5, l = tid & 31;
    const int mt  = w >> 1;          // m-tile (16 rows of s in G1 / c in G2)
    const int n0  = (w & 1) * 32;    // k-cluster half (4 n-tiles of 8)

    // ---- W -> bf16 hi/lo tiles [k][TSTR] ----
    {
        const int k = tid >> 3, cs = (tid & 7) * 16;
        const float* wg = convw + k * C_DIM + cs;
        #pragma unroll
        for (int g = 0; g < 2; g++) {
            uint32_t hh[4], ll[4];
            #pragma unroll
            for (int j = 0; j < 4; j++)
                hh[j] = pack_split(wg[8 * g + 2 * j], wg[8 * g + 2 * j + 1], ll[j]);
            *(uint4*)(smb + OFF_WH + k * TSTR + (cs + 8 * g) * 2) =
                make_uint4(hh[0], hh[1], hh[2], hh[3]);
            *(uint4*)(smb + OFF_WL + k * TSTR + (cs + 8 * g) * 2) =
                make_uint4(ll[0], ll[1], ll[2], ll[3]);
        }
    }

    float vacc[4][4];
    #pragma unroll
    for (int t = 0; t < 4; t++)
        #pragma unroll
        for (int i = 0; i < 4; i++) vacc[t][i] = 0.f;
    float asum = 0.f;

    const int chunk0 = sp * CPB;
    const int nch    = min(NCHUNK, chunk0 + CPB) - chunk0;
    const float* xb  = x + (size_t)n * C_DIM * S_TOT;

    // X staging: thread owns channel c = tid>>2, 32 pixels starting at (tid&3)*32
    const int Lc = tid >> 2, Ls0 = (tid & 3) * 32;
    float4 ld[8];
    {
        const float* g = xb + (size_t)Lc * S_TOT + chunk0 * SC + Ls0;
        #pragma unroll
        for (int r = 0; r < 8; r++) ld[r] = *(const float4*)(g + 4 * r);
    }

    for (int ci = 0; ci < nch; ci++) {
        __syncthreads();   // prev GEMM2 readers done -> Xc/P writable

        // ---- convert + store Xc hi/lo [c][s] ----
        #pragma unroll
        for (int g = 0; g < 4; g++) {
            float f[8] = { ld[2*g].x, ld[2*g].y, ld[2*g].z, ld[2*g].w,
                           ld[2*g+1].x, ld[2*g+1].y, ld[2*g+1].z, ld[2*g+1].w };
            uint32_t hh[4], ll[4];
            #pragma unroll
            for (int j = 0; j < 4; j++)
                hh[j] = pack_split(f[2*j], f[2*j+1], ll[j]);
            *(uint4*)(smb + OFF_XCH + Lc * TSTR + (Ls0 + 8*g) * 2) =
                make_uint4(hh[0], hh[1], hh[2], hh[3]);
            *(uint4*)(smb + OFF_XCL + Lc * TSTR + (Ls0 + 8*g) * 2) =
                make_uint4(ll[0], ll[1], ll[2], ll[3]);
        }
        __syncthreads();

        // ---- GEMM1: D1[s][k] = X^T W^T (A via ldmatrix.trans on Xc) ----
        {
            float d1[4][4];
            #pragma unroll
            for (int t = 0; t < 4; t++)
                #pragma unroll
                for (int i = 0; i < 4; i++) d1[t][i] = 0.f;

            const int s0 = mt * 16;
            const uint32_t raT = ((l >> 4) & 1) * 8 + (l & 7);
            const uint32_t caT = (s0 + ((l >> 3) & 1) * 8) * 2;
            const uint32_t rbB = (l & 7);
            const uint32_t cbB = ((l >> 3) & 1) * 16;

            #pragma unroll
            for (int kq = 0; kq < 8; kq++) {
                uint32_t Ah[4], Al[4];
                uint32_t ao = (kq * 16 + raT) * TSTR + caT;
                ldsm4t(Ah, sb + OFF_XCH + ao);
                ldsm4t(Al, sb + OFF_XCL + ao);
                #pragma unroll
                for (int nt = 0; nt < 4; nt++) {
                    uint32_t Bh[2], Bl[2];
                    uint32_t bo = (n0 + nt * 8 + rbB) * TSTR + kq * 32 + cbB;
                    ldsm2(Bh, sb + OFF_WH + bo);
                    ldsm2(Bl, sb + OFF_WL + bo);
                    mma16816(d1[nt], Ah, Bh);
                    mma16816(d1[nt], Al, Bh);
                    mma16816(d1[nt], Ah, Bl);
                }
            }
            // store D1 -> Ls fp32 [s][k]
            #pragma unroll
            for (int nt = 0; nt < 4; nt++)
                #pragma unroll
                for (int i = 0; i < 4; i++) {
                    int sr = s0 + (l >> 2) + (i >> 1) * 8;
                    int kk = n0 + nt * 8 + (l & 3) * 2 + (i & 1);
                    *(float*)(smb + OFF_LS + (sr * LSSTR + kk) * 4) = d1[nt][i];
                }
        }

        // ---- prefetch next chunk's X (hidden under softmax + GEMM2) ----
        if (ci + 1 < nch) {
            const float* g = xb + (size_t)Lc * S_TOT + (chunk0 + ci + 1) * SC + Ls0;
            #pragma unroll
            for (int r = 0; r < 8; r++) ld[r] = *(const float4*)(g + 4 * r);
        }
        __syncthreads();   // Ls complete

        // ---- softmax over k (thread = pixel s), write P hi/lo [k][s] ----
        if (tid < SC) {
            const char* row = smb + OFF_LS + tid * LSSTR * 4;
            float lg[64];
            #pragma unroll 8
            for (int k = 0; k < 64; k++) lg[k] = *(const float*)(row + 4 * k);
            float m = -1e30f;
            #pragma unroll 8
            for (int k = 0; k < 64; k++) m = fmaxf(m, lg[k]);
            float ssum = 0.f;
            #pragma unroll 8
            for (int k = 0; k < 64; k++) { lg[k] = __expf(lg[k] - m); ssum += lg[k]; }
            const float inv = 1.f / ssum;
            #pragma unroll 8
            for (int k = 0; k < 64; k++) {
                float p = lg[k] * inv;
                __nv_bfloat16 h = __float2bfloat16_rn(p);
                __nv_bfloat16 lo = __float2bfloat16_rn(p - __bfloat162float(h));
                *(__nv_bfloat16*)(smb + OFF_PH + k * TSTR + 2 * tid) = h;
                *(__nv_bfloat16*)(smb + OFF_PL + k * TSTR + 2 * tid) = lo;
            }
        }
        __syncthreads();   // P complete

        // ---- GEMM2: D2[c][k] += X P^T (register-accumulated across chunks) ----
        {
            const int c0 = mt * 16;
            const uint32_t raN = ((l >> 3) & 1) * 8 + (l & 7);
            const uint32_t caN = ((l >> 4) & 1) * 16;
            const uint32_t rbB = (l & 7);
            const uint32_t cbB = ((l >> 3) & 1) * 16;

            #pragma unroll
            for (int kq = 0; kq < 8; kq++) {
                uint32_t Ah[4], Al[4];
                uint32_t ao = (c0 + raN) * TSTR + kq * 32 + caN;
                ldsm4(Ah, sb + OFF_XCH + ao);
                ldsm4(Al, sb + OFF_XCL + ao);
                #pragma unroll
                for (int nt = 0; nt < 4; nt++) {
                    uint32_t Bh[2], Bl[2];
                    uint32_t bo = (n0 + nt * 8 + rbB) * TSTR + kq * 32 + cbB;
                    ldsm2(Bh, sb + OFF_PH + bo);
                    ldsm2(Bl, sb + OFF_PL + bo);
                    mma16816(vacc[nt], Ah, Bh);
                    mma16816(vacc[nt], Al, Bh);
                    mma16816(vacc[nt], Ah, Bl);
                }
            }
        }

        // ---- asum: per-cluster mass from P hi+lo (warps 8-9) ----
        // row = 128 pixels = 256 bytes -> 16 x 16B groups (R10 bug: was 8)
        if (tid >= 256 && tid < 320) {
            const int k = tid - 256;
            float a = 0.f;
            #pragma unroll
            for (int g = 0; g < 16; g++) {
                uint4 h4 = *(const uint4*)(smb + OFF_PH + k * TSTR + 16 * g);
                uint4 l4 = *(const uint4*)(smb + OFF_PL + k * TSTR + 16 * g);
                const uint32_t* hw = (const uint32_t*)&h4;
                const uint32_t* lw = (const uint32_t*)&l4;
                #pragma unroll
                for (int j = 0; j < 4; j++) {
                    float2 hp = __bfloat1622float2(*(__nv_bfloat162*)&hw[j]);
                    float2 lp = __bfloat1622float2(*(__nv_bfloat162*)&lw[j]);
                    a += hp.x + hp.y + lp.x + lp.y;
                }
            }
            asum += a;
        }
    }

    __syncthreads();   // last GEMM2 done -> Xc region reusable as vbuf

    // ---- write partials: vacc -> smem [k][130] -> coalesced gmem ----
    float* vbuf = (float*)smb;
    {
        const int c0 = mt * 16;
        #pragma unroll
        for (int nt = 0; nt < 4; nt++)
            #pragma unroll
            for (int i = 0; i < 4; i++) {
                int cc = c0 + (l >> 2) + (i >> 1) * 8;
                int kk = n0 + nt * 8 + (l & 3) * 2 + (i & 1);
                vbuf[kk * 130 + cc] = vacc[nt][i];
            }
    }
    if (tid >= 256 && tid < 320)
        g_apart[(n * SPLIT + sp) * K_CL + (tid - 256)] = asum;
    __syncthreads();

    float* vp = g_vpart + (size_t)(n * SPLIT + sp) * K_CL * C_DIM;
    #pragma unroll
    for (int r = 0; r < 16; r++) {
        int idx = tid + THREADS * r;
        vp[idx] = vbuf[(idx >> 7) * 130 + (idx & 127)];
    }
}

// ---- reduce partials, subtract a*cent, intra-normalize, partial global sums ----
__global__ void __launch_bounds__(256)
netvlad_reduce(const float* __restrict__ cent, float* __restrict__ out) {
    __shared__ float red[8];
    const int n   = blockIdx.y;
    const int kg  = blockIdx.x;
    const int tid = threadIdx.x;
    const int w   = tid >> 5, l = tid & 31;
    const int k   = kg * 8 + w;

    float as = 0.f;
    #pragma unroll
    for (int p = 0; p < SPLIT; p++) as += g_apart[(n * SPLIT + p) * K_CL + k];

    float4 v = make_float4(0.f, 0.f, 0.f, 0.f);
    #pragma unroll
    for (int p = 0; p < SPLIT; p++) {
        const float4* vp = (const float4*)(g_vpart +
            (size_t)(n * SPLIT + p) * K_CL * C_DIM + k * C_DIM);
        float4 t = vp[l];
        v.x += t.x; v.y += t.y; v.z += t.z; v.w += t.w;
    }
    float4 ct = ((const float4*)(cent + k * C_DIM))[l];
    v.x -= as * ct.x; v.y -= as * ct.y; v.z -= as * ct.z; v.w -= as * ct.w;

    float ss = v.x * v.x + v.y * v.y + v.z * v.z + v.w * v.w;
    #pragma unroll
    for (int o = 16; o; o >>= 1) ss += __shfl_xor_sync(0xffffffffu, ss, o);
    float inv = 1.f / fmaxf(sqrtf(ss), EPSV);
    v.x *= inv; v.y *= inv; v.z *= inv; v.w *= inv;
    ((float4*)(out + (size_t)n * K_CL * C_DIM + k * C_DIM))[l] = v;

    if (l == 0) red[w] = ss * inv * inv;
    __syncthreads();
    if (tid == 0) {
        float g = 0.f;
        #pragma unroll
        for (int i = 0; i < 8; i++) g += red[i];
        g_gsum[n * 8 + kg] = g;
    }
}

__global__ void __launch_bounds__(256)
netvlad_scale(float* __restrict__ out) {
    const int n   = blockIdx.x;
    const int tid = threadIdx.x;
    float g = 0.f;
    #pragma unroll
    for (int i = 0; i < 8; i++) g += g_gsum[n * 8 + i];
    const float ginv = 1.f / fmaxf(sqrtf(g), EPSV);

    float4* ob = (float4*)(out + (size_t)n * K_CL * C_DIM);
    #pragma unroll
    for (int r = 0; r < 8; r++) {
        float4 v = ob[tid + 256 * r];
        v.x *= ginv; v.y *= ginv; v.z *= ginv; v.w *= ginv;
        ob[tid + 256 * r] = v;
    }
}

extern "C" void kernel_launch(void* const* d_in, const int* in_sizes, int n_in,
                              void* d_out, int out_size) {
    const float* x     = (const float*)d_in[0];
    const float* convw = (const float*)d_in[1];
    const float* cent  = (const float*)d_in[2];
    float*       out   = (float*)d_out;

    cudaFuncSetAttribute(netvlad_main,
                         cudaFuncAttributeMaxDynamicSharedMemorySize, SMEM_BYTES);
    netvlad_main<<<dim3(SPLIT, N_IMG), THREADS, SMEM_BYTES>>>(x, convw);
    netvlad_reduce<<<dim3(8, N_IMG), 256>>>(cent, out);
    netvlad_scale<<<N_IMG, 256>>>(out);
}

// round 12
// speedup vs baseline: 2.0982x; 1.5625x over previous
#include <cuda_runtime.h>
#include <cuda_bf16.h>
#include <cstdint>
#include <math.h>

#define N_IMG   32
#define C_DIM   128
#define K_CL    64
#define S_TOT   12544
#define SC      128
#define NCHUNK  98
#define SPLIT   9
#define CPB     11
#define THREADS 512
#define EPSV    1e-12f
#define HS      64          // half-chunk pixels

#define XSTR    144         // X tile row stride bytes (128+16; 9 mod 8 =1 -> ldsm ok)
#define PSTR    144
#define WSTR    272         // W row stride (256+16; 17 mod 8 =1 -> ldsm ok)
#define LSW     68          // Ls row stride in words

// smem byte offsets
#define OFF_XH0 0
#define OFF_XL0 (OFF_XH0 + 128 * XSTR)
#define OFF_XH1 (OFF_XL0 + 128 * XSTR)
#define OFF_XL1 (OFF_XH1 + 128 * XSTR)
#define OFF_WH  (OFF_XL1 + 128 * XSTR)      //  73728
#define OFF_WL  (OFF_WH  +  64 * WSTR)
#define OFF_LS0 (OFF_WL  +  64 * WSTR)      // 108544
#define OFF_LS1 (OFF_LS0 +  64 * LSW * 4)
#define OFF_PH  (OFF_LS1 +  64 * LSW * 4)   // 143360
#define OFF_PL  (OFF_PH  +  64 * PSTR)
#define SMEM_BYTES (OFF_PL + 64 * PSTR)     // 161792

// named barriers (0 reserved for __syncthreads)
#define BID_LSFULL 1    // +b
#define BID_LSFREE 3    // +b
#define BID_XFREE  5    // +b
#define BID_G1LOC  7
#define BID_G2LOC  8

__device__ float g_vpart[(size_t)N_IMG * SPLIT * K_CL * C_DIM];
__device__ float g_apart[N_IMG * SPLIT * K_CL];
__device__ float g_gsum[N_IMG * 8];

// ---------------- PTX helpers ----------------
__device__ __forceinline__ void bar_sync(int id, int cnt) {
    asm volatile("bar.sync %0, %1;" :: "r"(id), "r"(cnt) : "memory");
}
__device__ __forceinline__ void bar_arrive(int id, int cnt) {
    asm volatile("bar.arrive %0, %1;" :: "r"(id), "r"(cnt) : "memory");
}
__device__ __forceinline__ void ldsm4(uint32_t* r, uint32_t a) {
    asm volatile("ldmatrix.sync.aligned.m8n8.x4.shared.b16 {%0,%1,%2,%3}, [%4];"
        : "=r"(r[0]), "=r"(r[1]), "=r"(r[2]), "=r"(r[3]) : "r"(a));
}
__device__ __forceinline__ void ldsm4t(uint32_t* r, uint32_t a) {
    asm volatile("ldmatrix.sync.aligned.m8n8.x4.trans.shared.b16 {%0,%1,%2,%3}, [%4];"
        : "=r"(r[0]), "=r"(r[1]), "=r"(r[2]), "=r"(r[3]) : "r"(a));
}
__device__ __forceinline__ void mma16816(float* d, const uint32_t* a, const uint32_t* b) {
    asm volatile("mma.sync.aligned.m16n8k16.row.col.f32.bf16.bf16.f32 "
        "{%0,%1,%2,%3}, {%4,%5,%6,%7}, {%8,%9}, {%0,%1,%2,%3};"
        : "+f"(d[0]), "+f"(d[1]), "+f"(d[2]), "+f"(d[3])
        : "r"(a[0]), "r"(a[1]), "r"(a[2]), "r"(a[3]), "r"(b[0]), "r"(b[1]));
}
__device__ __forceinline__ uint32_t pack_split(float a, float b, uint32_t& lo) {
    __nv_bfloat16 ah = __float2bfloat16_rn(a);
    __nv_bfloat16 bh = __float2bfloat16_rn(b);
    __nv_bfloat16 al = __float2bfloat16_rn(a - __bfloat162float(ah));
    __nv_bfloat16 bl = __float2bfloat16_rn(b - __bfloat162float(bh));
    lo = (uint32_t)__bfloat16_as_ushort(al) | ((uint32_t)__bfloat16_as_ushort(bl) << 16);
    return (uint32_t)__bfloat16_as_ushort(ah) | ((uint32_t)__bfloat16_as_ushort(bh) << 16);
}

__global__ void __launch_bounds__(THREADS, 1)
netvlad_main(const float* __restrict__ x, const float* __restrict__ convw) {
    extern __shared__ char smb[];
    const uint32_t sb = (uint32_t)__cvta_generic_to_shared(smb);

    const int n   = blockIdx.y;
    const int sp  = blockIdx.x;
    const int tid = threadIdx.x;
    const int w   = tid >> 5, l = tid & 31;

    // ---- W -> bf16 hi/lo tiles [k][WSTR] (all 512 threads) ----
    {
        const int k = tid >> 3, cs = (tid & 7) * 16;
        const float* wg = convw + k * C_DIM + cs;
        #pragma unroll
        for (int g = 0; g < 2; g++) {
            uint32_t hh[4], ll[4];
            #pragma unroll
            for (int j = 0; j < 4; j++)
                hh[j] = pack_split(wg[8 * g + 2 * j], wg[8 * g + 2 * j + 1], ll[j]);
            *(uint4*)(smb + OFF_WH + k * WSTR + (cs + 8 * g) * 2) =
                make_uint4(hh[0], hh[1], hh[2], hh[3]);
            *(uint4*)(smb + OFF_WL + k * WSTR + (cs + 8 * g) * 2) =
                make_uint4(ll[0], ll[1], ll[2], ll[3]);
        }
    }
    __syncthreads();

    const int chunk0 = sp * CPB;
    const int nch    = min(NCHUNK, chunk0 + CPB) - chunk0;
    const int nH     = nch * 2;
    const int sbase  = chunk0 * SC;
    const float* xb  = x + (size_t)n * C_DIM * S_TOT;

    const uint32_t XH[2] = { sb + OFF_XH0, sb + OFF_XH1 };
    const uint32_t XL[2] = { sb + OFF_XL0, sb + OFF_XL1 };
    const uint32_t LSO[2] = { sb + OFF_LS0, sb + OFF_LS1 };

    if (w < 8) {
        // ================= G1 group: convert X + GEMM1 =================
        const int Lc = tid >> 1;            // channel 0..127
        const int Lh = tid & 1;             // 32-pixel half
        const int mt = w >> 1, n0 = (w & 1) * 32, s0 = mt * 16;
        const uint32_t raT = ((l >> 4) & 1) * 8 + (l & 7);
        const uint32_t caT = (s0 + ((l >> 3) & 1) * 8) * 2;
        const uint32_t rbX = ((l >> 4) & 1) * 8 + (l & 7);   // B x4 rows
        const uint32_t cb16 = ((l >> 3) & 1) * 16;

        float4 ld[8];
        {
            const float* g = xb + (size_t)Lc * S_TOT + sbase + Lh * 32;
            #pragma unroll
            for (int r = 0; r < 8; r++) ld[r] = *(const float4*)(g + 4 * r);
        }

        for (int j = 0; j < nH; j++) {
            const int b = j & 1;
            if (j >= 2) bar_sync(BID_XFREE + b, 512);

            // convert & store X[b] hi/lo (32 px per thread)
            const uint32_t xo = Lc * XSTR + Lh * 64;
            #pragma unroll
            for (int g4 = 0; g4 < 4; g4++) {
                float f[8] = { ld[2*g4].x, ld[2*g4].y, ld[2*g4].z, ld[2*g4].w,
                               ld[2*g4+1].x, ld[2*g4+1].y, ld[2*g4+1].z, ld[2*g4+1].w };
                uint32_t hh[4], ll[4];
                #pragma unroll
                for (int jj2 = 0; jj2 < 4; jj2++)
                    hh[jj2] = pack_split(f[2*jj2], f[2*jj2+1], ll[jj2]);
                *(uint4*)(smb + (XH[b] - sb) + xo + 16 * g4) =
                    make_uint4(hh[0], hh[1], hh[2], hh[3]);
                *(uint4*)(smb + (XL[b] - sb) + xo + 16 * g4) =
                    make_uint4(ll[0], ll[1], ll[2], ll[3]);
            }
            bar_sync(BID_G1LOC, 256);

            // prefetch next half-chunk
            if (j + 1 < nH) {
                const float* g = xb + (size_t)Lc * S_TOT + sbase + (j + 1) * HS + Lh * 32;
                #pragma unroll
                for (int r = 0; r < 8; r++) ld[r] = *(const float4*)(g + 4 * r);
            }

            // GEMM1: D1[s][k] = X^T W^T over c=128 (8 kq)
            float d1[4][4];
            #pragma unroll
            for (int t = 0; t < 4; t++)
                #pragma unroll
                for (int i = 0; i < 4; i++) d1[t][i] = 0.f;

            #pragma unroll
            for (int kq = 0; kq < 8; kq++) {
                uint32_t Ah[4], Al[4];
                const uint32_t ao = (kq * 16 + raT) * XSTR + caT;
                ldsm4t(Ah, XH[b] + ao);
                ldsm4t(Al, XL[b] + ao);
                #pragma unroll
                for (int ntp = 0; ntp < 2; ntp++) {
                    uint32_t Bh[4], Bl[4];
                    const uint32_t bo = (n0 + ntp * 16 + rbX) * WSTR + kq * 32 + cb16;
                    ldsm4(Bh, sb + OFF_WH + bo);
                    ldsm4(Bl, sb + OFF_WL + bo);
                    mma16816(d1[2*ntp],   Ah, Bh);     mma16816(d1[2*ntp],   Al, Bh);
                    mma16816(d1[2*ntp],   Ah, Bl);
                    mma16816(d1[2*ntp+1], Ah, Bh + 2); mma16816(d1[2*ntp+1], Al, Bh + 2);
                    mma16816(d1[2*ntp+1], Ah, Bl + 2);
                }
            }

            if (j >= 2) bar_sync(BID_LSFREE + b, 512);
            float* Lsb = (float*)(smb + (LSO[b] - sb));
            #pragma unroll
            for (int nt = 0; nt < 4; nt++)
                #pragma unroll
                for (int i = 0; i < 4; i++) {
                    int sr = s0 + (l >> 2) + (i >> 1) * 8;
                    int kk = n0 + nt * 8 + (l & 3) * 2 + (i & 1);
                    Lsb[sr * LSW + kk] = d1[nt][i];
                }
            bar_arrive(BID_LSFULL + b, 512);
        }
    } else {
        // ================= G2 group: softmax + GEMM2 + asum =================
        const int t2 = tid - 256;
        const int wi = w - 8;
        const int n0 = (wi & 1) * 32, ct0 = (wi >> 1) * 2;
        const int p = t2 >> 2, q = t2 & 3;
        const uint32_t raN = ((l >> 3) & 1) * 8 + (l & 7);
        const uint32_t caN = ((l >> 4) & 1) * 16;
        const uint32_t rbX = ((l >> 4) & 1) * 8 + (l & 7);
        const uint32_t cb16 = ((l >> 3) & 1) * 16;

        float vacc[2][4][4];
        #pragma unroll
        for (int c = 0; c < 2; c++)
            #pragma unroll
            for (int t = 0; t < 4; t++)
                #pragma unroll
                for (int i = 0; i < 4; i++) vacc[c][t][i] = 0.f;
        float asum = 0.f;

        for (int jj = 0; jj < nH; jj++) {
            const int b = jj & 1;
            bar_sync(BID_LSFULL + b, 512);

            // load logits: k = q + 4*jx  (conflict-free scalar reads)
            const float* Lsb = (const float*)(smb + (LSO[b] - sb)) + p * LSW + q;
            float lg[16];
            #pragma unroll
            for (int jx = 0; jx < 16; jx++) lg[jx] = Lsb[4 * jx];
            bar_arrive(BID_LSFREE + b, 512);

            // softmax over 64 k (4 lanes per pixel, shuffle over q)
            float m = lg[0];
            #pragma unroll
            for (int jx = 1; jx < 16; jx++) m = fmaxf(m, lg[jx]);
            m = fmaxf(m, __shfl_xor_sync(0xffffffffu, m, 1));
            m = fmaxf(m, __shfl_xor_sync(0xffffffffu, m, 2));
            float ssum = 0.f;
            #pragma unroll
            for (int jx = 0; jx < 16; jx++) { lg[jx] = __expf(lg[jx] - m); ssum += lg[jx]; }
            ssum += __shfl_xor_sync(0xffffffffu, ssum, 1);
            ssum += __shfl_xor_sync(0xffffffffu, ssum, 2);
            const float inv = 1.f / ssum;

            #pragma unroll
            for (int jx = 0; jx < 16; jx++) {
                float pv = lg[jx] * inv;
                __nv_bfloat16 h  = __float2bfloat16_rn(pv);
                __nv_bfloat16 lo = __float2bfloat16_rn(pv - __bfloat162float(h));
                const int k = q + 4 * jx;
                *(__nv_bfloat16*)(smb + OFF_PH + k * PSTR + 2 * p) = h;
                *(__nv_bfloat16*)(smb + OFF_PL + k * PSTR + 2 * p) = lo;
            }
            bar_sync(BID_G2LOC, 256);

            // asum (warps 8-9: one k row each, 64 px)
            if (t2 < 64) {
                float a = 0.f;
                #pragma unroll
                for (int g = 0; g < 4; g++) {
                    uint4 h4 = *(const uint4*)(smb + OFF_PH + t2 * PSTR + 16 * g);
                    uint4 l4 = *(const uint4*)(smb + OFF_PL + t2 * PSTR + 16 * g);
                    uint4 h5 = *(const uint4*)(smb + OFF_PH + t2 * PSTR + 64 + 16 * g);
                    uint4 l5 = *(const uint4*)(smb + OFF_PL + t2 * PSTR + 64 + 16 * g);
                    const uint32_t* hw = (const uint32_t*)&h4;
                    const uint32_t* lw = (const uint32_t*)&l4;
                    const uint32_t* hw2 = (const uint32_t*)&h5;
                    const uint32_t* lw2 = (const uint32_t*)&l5;
                    #pragma unroll
                    for (int jx = 0; jx < 4; jx++) {
                        float2 a1 = __bfloat1622float2(*(__nv_bfloat162*)&hw[jx]);
                        float2 a2 = __bfloat1622float2(*(__nv_bfloat162*)&lw[jx]);
                        float2 a3 = __bfloat1622float2(*(__nv_bfloat162*)&hw2[jx]);
                        float2 a4 = __bfloat1622float2(*(__nv_bfloat162*)&lw2[jx]);
                        a += a1.x + a1.y + a2.x + a2.y + a3.x + a3.y + a4.x + a4.y;
                    }
                }
                asum += a;
            }

            // GEMM2: D2[c][k] += X P^T over s=64 (4 sq)
            #pragma unroll
            for (int sq = 0; sq < 4; sq++) {
                uint32_t Bh[2][4], Bl[2][4];
                #pragma unroll
                for (int ntp = 0; ntp < 2; ntp++) {
                    const uint32_t bo = (n0 + ntp * 16 + rbX) * PSTR + sq * 32 + cb16;
                    ldsm4(Bh[ntp], sb + OFF_PH + bo);
                    ldsm4(Bl[ntp], sb + OFF_PL + bo);
                }
                #pragma unroll
                for (int cti = 0; cti < 2; cti++) {
                    uint32_t Ah[4], Al[4];
                    const uint32_t ao = ((ct0 + cti) * 16 + raN) * XSTR + sq * 32 + caN;
                    ldsm4(Ah, XH[b] + ao);
                    ldsm4(Al, XL[b] + ao);
                    #pragma unroll
                    for (int ntp = 0; ntp < 2; ntp++) {
                        mma16816(vacc[cti][2*ntp],   Ah, Bh[ntp]);
                        mma16816(vacc[cti][2*ntp],   Al, Bh[ntp]);
                        mma16816(vacc[cti][2*ntp],   Ah, Bl[ntp]);
                        mma16816(vacc[cti][2*ntp+1], Ah, Bh[ntp] + 2);
                        mma16816(vacc[cti][2*ntp+1], Al, Bh[ntp] + 2);
                        mma16816(vacc[cti][2*ntp+1], Ah, Bl[ntp] + 2);
                    }
                }
            }
            bar_arrive(BID_XFREE + b, 512);
        }

        if (t2 < 64) g_apart[(n * SPLIT + sp) * K_CL + t2] = asum;

        __syncthreads();   // join with G1
        // write vacc -> vbuf [k][130] (reuse X region)
        float* vbuf = (float*)smb;
        #pragma unroll
        for (int cti = 0; cti < 2; cti++)
            #pragma unroll
            for (int nt = 0; nt < 4; nt++)
                #pragma unroll
                for (int i = 0; i < 4; i++) {
                    int cc = (ct0 + cti) * 16 + (l >> 2) + (i >> 1) * 8;
                    int kk = n0 + nt * 8 + (l & 3) * 2 + (i & 1);
                    vbuf[kk * 130 + cc] = vacc[cti][nt][i];
                }
    }
    if (w < 8) __syncthreads();   // G1 side of the join barrier
    __syncthreads();

    float* vp = g_vpart + (size_t)(n * SPLIT + sp) * K_CL * C_DIM;
    const float* vbuf = (const float*)smb;
    #pragma unroll
    for (int r = 0; r < 16; r++) {
        int idx = tid + THREADS * r;
        vp[idx] = vbuf[(idx >> 7) * 130 + (idx & 127)];
    }
}

// ---- reduce partials, subtract a*cent, intra-normalize, partial global sums ----
__global__ void __launch_bounds__(256)
netvlad_reduce(const float* __restrict__ cent, float* __restrict__ out) {
    __shared__ float red[8];
    const int n   = blockIdx.y;
    const int kg  = blockIdx.x;
    const int tid = threadIdx.x;
    const int w   = tid >> 5, l = tid & 31;
    const int k   = kg * 8 + w;

    float as = 0.f;
    #pragma unroll
    for (int p = 0; p < SPLIT; p++) as += g_apart[(n * SPLIT + p) * K_CL + k];

    float4 v = make_float4(0.f, 0.f, 0.f, 0.f);
    #pragma unroll
    for (int p = 0; p < SPLIT; p++) {
        const float4* vp = (const float4*)(g_vpart +
            (size_t)(n * SPLIT + p) * K_CL * C_DIM + k * C_DIM);
        float4 t = vp[l];
        v.x += t.x; v.y += t.y; v.z += t.z; v.w += t.w;
    }
    float4 ct = ((const float4*)(cent + k * C_DIM))[l];
    v.x -= as * ct.x; v.y -= as * ct.y; v.z -= as * ct.z; v.w -= as * ct.w;

    float ss = v.x * v.x + v.y * v.y + v.z * v.z + v.w * v.w;
    #pragma unroll
    for (int o = 16; o; o >>= 1) ss += __shfl_xor_sync(0xffffffffu, ss, o);
    float inv = 1.f / fmaxf(sqrtf(ss), EPSV);
    v.x *= inv; v.y *= inv; v.z *= inv; v.w *= inv;
    ((float4*)(out + (size_t)n * K_CL * C_DIM + k * C_DIM))[l] = v;

    if (l == 0) red[w] = ss * inv * inv;
    __syncthreads();
    if (tid == 0) {
        float g = 0.f;
        #pragma unroll
        for (int i = 0; i < 8; i++) g += red[i];
        g_gsum[n * 8 + kg] = g;
    }
}

__global__ void __launch_bounds__(256)
netvlad_scale(float* __restrict__ out) {
    const int n   = blockIdx.x;
    const int tid = threadIdx.x;
    float g = 0.f;
    #pragma unroll
    for (int i = 0; i < 8; i++) g += g_gsum[n * 8 + i];
    const float ginv = 1.f / fmaxf(sqrtf(g), EPSV);

    float4* ob = (float4*)(out + (size_t)n * K_CL * C_DIM);
    #pragma unroll
    for (int r = 0; r < 8; r++) {
        float4 v = ob[tid + 256 * r];
        v.x *= ginv; v.y *= ginv; v.z *= ginv; v.w *= ginv;
        ob[tid + 256 * r] = v;
    }
}

extern "C" void kernel_launch(void* const* d_in, const int* in_sizes, int n_in,
                              void* d_out, int out_size) {
    const float* x     = (const float*)d_in[0];
    const float* convw = (const float*)d_in[1];
    const float* cent  = (const float*)d_in[2];
    float*       out   = (float*)d_out;

    cudaFuncSetAttribute(netvlad_main,
                         cudaFuncAttributeMaxDynamicSharedMemorySize, SMEM_BYTES);
    netvlad_main<<<dim3(SPLIT, N_IMG), THREADS, SMEM_BYTES>>>(x, convw);
    netvlad_reduce<<<dim3(8, N_IMG), 256>>>(cent, out);
    netvlad_scale<<<N_IMG, 256>>>(out);
}

// round 14
// speedup vs baseline: 2.3927x; 1.1404x over previous
#include <cuda_runtime.h>
#include <cuda_bf16.h>
#include <cstdint>
#include <math.h>

#define N_IMG   32
#define C_DIM   128
#define K_CL    64
#define S_TOT   12544
#define SC      128
#define NCHUNK  98
#define SPLIT   9
#define CPB     11
#define THREADS 512
#define EPSV    1e-12f
#define HS      64          // half-chunk pixels

#define XSTR    144         // X tile row stride bytes
#define PSTR    144
#define WSTR    272         // W row stride bytes
#define LSW     68          // Ls row stride in words

// smem byte offsets
#define OFF_XH0 0
#define OFF_XL0 (OFF_XH0 + 128 * XSTR)
#define OFF_XH1 (OFF_XL0 + 128 * XSTR)
#define OFF_XL1 (OFF_XH1 + 128 * XSTR)
#define OFF_WH  (OFF_XL1 + 128 * XSTR)      //  73728
#define OFF_LS0 (OFF_WH  +  64 * WSTR)      //  91136
#define OFF_LS1 (OFF_LS0 +  64 * LSW * 4)
#define OFF_PH  (OFF_LS1 +  64 * LSW * 4)   // 125952
#define OFF_ASR (OFF_PH  +  64 * PSTR)      // 135168  (8 warps x 64 floats)
#define SMEM_BYTES (OFF_ASR + 8 * 64 * 4)   // 137216

// named barriers (0 reserved for __syncthreads)
#define BID_LSFULL 1    // +b
#define BID_LSFREE 3    // +b
#define BID_XFREE  5    // +b
#define BID_G1LOC  7
#define BID_G2LOC  8

__device__ float g_vpart[(size_t)N_IMG * SPLIT * K_CL * C_DIM];
__device__ float g_apart[N_IMG * SPLIT * K_CL];
__device__ float g_gsum[N_IMG * 8];

// ---------------- PTX helpers ----------------
__device__ __forceinline__ void bar_sync(int id, int cnt) {
    asm volatile("bar.sync %0, %1;" :: "r"(id), "r"(cnt) : "memory");
}
__device__ __forceinline__ void bar_arrive(int id, int cnt) {
    asm volatile("bar.arrive %0, %1;" :: "r"(id), "r"(cnt) : "memory");
}
__device__ __forceinline__ void ldsm4(uint32_t* r, uint32_t a) {
    asm volatile("ldmatrix.sync.aligned.m8n8.x4.shared.b16 {%0,%1,%2,%3}, [%4];"
        : "=r"(r[0]), "=r"(r[1]), "=r"(r[2]), "=r"(r[3]) : "r"(a));
}
__device__ __forceinline__ void ldsm4t(uint32_t* r, uint32_t a) {
    asm volatile("ldmatrix.sync.aligned.m8n8.x4.trans.shared.b16 {%0,%1,%2,%3}, [%4];"
        : "=r"(r[0]), "=r"(r[1]), "=r"(r[2]), "=r"(r[3]) : "r"(a));
}
__device__ __forceinline__ void mma16816(float* d, const uint32_t* a, const uint32_t* b) {
    asm volatile("mma.sync.aligned.m16n8k16.row.col.f32.bf16.bf16.f32 "
        "{%0,%1,%2,%3}, {%4,%5,%6,%7}, {%8,%9}, {%0,%1,%2,%3};"
        : "+f"(d[0]), "+f"(d[1]), "+f"(d[2]), "+f"(d[3])
        : "r"(a[0]), "r"(a[1]), "r"(a[2]), "r"(a[3]), "r"(b[0]), "r"(b[1]));
}
__device__ __forceinline__ uint32_t pack_split(float a, float b, uint32_t& lo) {
    __nv_bfloat16 ah = __float2bfloat16_rn(a);
    __nv_bfloat16 bh = __float2bfloat16_rn(b);
    __nv_bfloat16 al = __float2bfloat16_rn(a - __bfloat162float(ah));
    __nv_bfloat16 bl = __float2bfloat16_rn(b - __bfloat162float(bh));
    lo = (uint32_t)__bfloat16_as_ushort(al) | ((uint32_t)__bfloat16_as_ushort(bl) << 16);
    return (uint32_t)__bfloat16_as_ushort(ah) | ((uint32_t)__bfloat16_as_ushort(bh) << 16);
}
__device__ __forceinline__ uint32_t pack_hi(float a, float b) {
    __nv_bfloat16 ah = __float2bfloat16_rn(a);
    __nv_bfloat16 bh = __float2bfloat16_rn(b);
    return (uint32_t)__bfloat16_as_ushort(ah) | ((uint32_t)__bfloat16_as_ushort(bh) << 16);
}

__global__ void __launch_bounds__(THREADS, 1)
netvlad_main(const float* __restrict__ x, const float* __restrict__ convw) {
    extern __shared__ char smb[];
    const uint32_t sb = (uint32_t)__cvta_generic_to_shared(smb);

    const int n   = blockIdx.y;
    const int sp  = blockIdx.x;
    const int tid = threadIdx.x;
    const int w   = tid >> 5, l = tid & 31;

    // ---- W -> bf16 hi tile [k][WSTR] (all 512 threads); W_lo dropped ----
    {
        const int k = tid >> 3, cs = (tid & 7) * 16;
        const float* wg = convw + k * C_DIM + cs;
        #pragma unroll
        for (int g = 0; g < 2; g++) {
            uint32_t hh[4];
            #pragma unroll
            for (int j = 0; j < 4; j++)
                hh[j] = pack_hi(wg[8 * g + 2 * j], wg[8 * g + 2 * j + 1]);
            *(uint4*)(smb + OFF_WH + k * WSTR + (cs + 8 * g) * 2) =
                make_uint4(hh[0], hh[1], hh[2], hh[3]);
        }
    }
    __syncthreads();

    const int chunk0 = sp * CPB;
    const int nch    = min(NCHUNK, chunk0 + CPB) - chunk0;
    const int nH     = nch * 2;
    const int sbase  = chunk0 * SC;
    const float* xb  = x + (size_t)n * C_DIM * S_TOT;

    const uint32_t XH[2] = { sb + OFF_XH0, sb + OFF_XH1 };
    const uint32_t XL[2] = { sb + OFF_XL0, sb + OFF_XL1 };
    const uint32_t LSO[2] = { sb + OFF_LS0, sb + OFF_LS1 };

    if (w < 8) {
        // ================= G1 group: convert X + GEMM1 =================
        const int Lc = tid >> 1;            // channel 0..127
        const int Lh = tid & 1;             // 32-pixel half
        const int mt = w >> 1, n0 = (w & 1) * 32, s0 = mt * 16;
        const uint32_t raT = ((l >> 4) & 1) * 8 + (l & 7);
        const uint32_t caT = (s0 + ((l >> 3) & 1) * 8) * 2;
        const uint32_t rbX = ((l >> 4) & 1) * 8 + (l & 7);
        const uint32_t cb16 = ((l >> 3) & 1) * 16;

        float4 ld[8];
        {
            const float* g = xb + (size_t)Lc * S_TOT + sbase + Lh * 32;
            #pragma unroll
            for (int r = 0; r < 8; r++) ld[r] = *(const float4*)(g + 4 * r);
        }

        for (int j = 0; j < nH; j++) {
            const int b = j & 1;
            if (j >= 2) bar_sync(BID_XFREE + b, 512);

            // convert & store X[b] hi/lo (32 px per thread)
            const uint32_t xo = Lc * XSTR + Lh * 64;
            #pragma unroll
            for (int g4 = 0; g4 < 4; g4++) {
                float f[8] = { ld[2*g4].x, ld[2*g4].y, ld[2*g4].z, ld[2*g4].w,
                               ld[2*g4+1].x, ld[2*g4+1].y, ld[2*g4+1].z, ld[2*g4+1].w };
                uint32_t hh[4], ll[4];
                #pragma unroll
                for (int jj2 = 0; jj2 < 4; jj2++)
                    hh[jj2] = pack_split(f[2*jj2], f[2*jj2+1], ll[jj2]);
                *(uint4*)(smb + (XH[b] - sb) + xo + 16 * g4) =
                    make_uint4(hh[0], hh[1], hh[2], hh[3]);
                *(uint4*)(smb + (XL[b] - sb) + xo + 16 * g4) =
                    make_uint4(ll[0], ll[1], ll[2], ll[3]);
            }
            bar_sync(BID_G1LOC, 256);

            // prefetch next half-chunk
            if (j + 1 < nH) {
                const float* g = xb + (size_t)Lc * S_TOT + sbase + (j + 1) * HS + Lh * 32;
                #pragma unroll
                for (int r = 0; r < 8; r++) ld[r] = *(const float4*)(g + 4 * r);
            }

            // GEMM1: D1[s][k] = X^T W^T over c=128 (8 kq); 2-pass (hh + lh)
            float d1[4][4];
            #pragma unroll
            for (int t = 0; t < 4; t++)
                #pragma unroll
                for (int i = 0; i < 4; i++) d1[t][i] = 0.f;

            #pragma unroll
            for (int kq = 0; kq < 8; kq++) {
                uint32_t Ah[4], Al[4];
                const uint32_t ao = (kq * 16 + raT) * XSTR + caT;
                ldsm4t(Ah, XH[b] + ao);
                ldsm4t(Al, XL[b] + ao);
                #pragma unroll
                for (int ntp = 0; ntp < 2; ntp++) {
                    uint32_t Bh[4];
                    const uint32_t bo = (n0 + ntp * 16 + rbX) * WSTR + kq * 32 + cb16;
                    ldsm4(Bh, sb + OFF_WH + bo);
                    mma16816(d1[2*ntp],   Ah, Bh);     mma16816(d1[2*ntp],   Al, Bh);
                    mma16816(d1[2*ntp+1], Ah, Bh + 2); mma16816(d1[2*ntp+1], Al, Bh + 2);
                }
            }

            if (j >= 2) bar_sync(BID_LSFREE + b, 512);
            float* Lsb = (float*)(smb + (LSO[b] - sb));
            #pragma unroll
            for (int nt = 0; nt < 4; nt++)
                #pragma unroll
                for (int i = 0; i < 4; i++) {
                    int sr = s0 + (l >> 2) + (i >> 1) * 8;
                    int kk = n0 + nt * 8 + (l & 3) * 2 + (i & 1);
                    Lsb[sr * LSW + kk] = d1[nt][i];
                }
            bar_arrive(BID_LSFULL + b, 512);
        }
    } else {
        // ================= G2 group: softmax + GEMM2 + asum =================
        const int t2 = tid - 256;
        const int wi = w - 8;
        const int n0 = (wi & 1) * 32, ct0 = (wi >> 1) * 2;
        const int p = t2 >> 2, q = t2 & 3;
        const uint32_t raN = ((l >> 3) & 1) * 8 + (l & 7);
        const uint32_t caN = ((l >> 4) & 1) * 16;
        const uint32_t rbX = ((l >> 4) & 1) * 8 + (l & 7);
        const uint32_t cb16 = ((l >> 3) & 1) * 16;

        float vacc[2][4][4];
        #pragma unroll
        for (int c = 0; c < 2; c++)
            #pragma unroll
            for (int t = 0; t < 4; t++)
                #pragma unroll
                for (int i = 0; i < 4; i++) vacc[c][t][i] = 0.f;
        float asum_loc[16];
        #pragma unroll
        for (int jx = 0; jx < 16; jx++) asum_loc[jx] = 0.f;

        for (int jj = 0; jj < nH; jj++) {
            const int b = jj & 1;
            bar_sync(BID_LSFULL + b, 512);

            // load logits: k = q + 4*jx  (conflict-free scalar reads)
            const float* Lsb = (const float*)(smb + (LSO[b] - sb)) + p * LSW + q;
            float lg[16];
            #pragma unroll
            for (int jx = 0; jx < 16; jx++) lg[jx] = Lsb[4 * jx];
            bar_arrive(BID_LSFREE + b, 512);

            // softmax over 64 k (4 lanes per pixel, shuffle over q)
            float m = lg[0];
            #pragma unroll
            for (int jx = 1; jx < 16; jx++) m = fmaxf(m, lg[jx]);
            m = fmaxf(m, __shfl_xor_sync(0xffffffffu, m, 1));
            m = fmaxf(m, __shfl_xor_sync(0xffffffffu, m, 2));
            float ssum = 0.f;
            #pragma unroll
            for (int jx = 0; jx < 16; jx++) { lg[jx] = __expf(lg[jx] - m); ssum += lg[jx]; }
            ssum += __shfl_xor_sync(0xffffffffu, ssum, 1);
            ssum += __shfl_xor_sync(0xffffffffu, ssum, 2);
            const float inv = 1.f / ssum;

            #pragma unroll
            for (int jx = 0; jx < 16; jx++) {
                float pv = lg[jx] * inv;
                asum_loc[jx] += pv;                       // exact fp32 mass
                __nv_bfloat16 h = __float2bfloat16_rn(pv);
                const int k = q + 4 * jx;
                *(__nv_bfloat16*)(smb + OFF_PH + k * PSTR + 2 * p) = h;
            }
            bar_sync(BID_G2LOC, 256);

            // GEMM2: D2[c][k] += X P^T over s=64 (4 sq); 2-pass (hh + lh)
            #pragma unroll
            for (int sq = 0; sq < 4; sq++) {
                uint32_t Bh[2][4];
                #pragma unroll
                for (int ntp = 0; ntp < 2; ntp++) {
                    const uint32_t bo = (n0 + ntp * 16 + rbX) * PSTR + sq * 32 + cb16;
                    ldsm4(Bh[ntp], sb + OFF_PH + bo);
                }
                #pragma unroll
                for (int cti = 0; cti < 2; cti++) {
                    uint32_t Ah[4], Al[4];
                    const uint32_t ao = ((ct0 + cti) * 16 + raN) * XSTR + sq * 32 + caN;
                    ldsm4(Ah, XH[b] + ao);
                    ldsm4(Al, XL[b] + ao);
                    #pragma unroll
                    for (int ntp = 0; ntp < 2; ntp++) {
                        mma16816(vacc[cti][2*ntp],   Ah, Bh[ntp]);
                        mma16816(vacc[cti][2*ntp],   Al, Bh[ntp]);
                        mma16816(vacc[cti][2*ntp+1], Ah, Bh[ntp] + 2);
                        mma16816(vacc[cti][2*ntp+1], Al, Bh[ntp] + 2);
                    }
                }
            }
            bar_arrive(BID_XFREE + b, 512);
        }

        // ---- asum end reduction: over p (8 in-warp via shfl, 8 warps via smem) ----
        {
            float* asred = (float*)(smb + OFF_ASR);
            #pragma unroll
            for (int jx = 0; jx < 16; jx++) {
                float v = asum_loc[jx];
                v += __shfl_xor_sync(0xffffffffu, v, 4);
                v += __shfl_xor_sync(0xffffffffu, v, 8);
                v += __shfl_xor_sync(0xffffffffu, v, 16);
                if (l < 4) asred[wi * 64 + l + 4 * jx] = v;
            }
            bar_sync(BID_G2LOC, 256);
            if (t2 < 64) {
                float a = 0.f;
                #pragma unroll
                for (int i = 0; i < 8; i++) a += asred[i * 64 + t2];
                g_apart[(n * SPLIT + sp) * K_CL + t2] = a;
            }
        }

        __syncthreads();   // join with G1
        // write vacc -> vbuf [k][130] (reuse X region)
        float* vbuf = (float*)smb;
        #pragma unroll
        for (int cti = 0; cti < 2; cti++)
            #pragma unroll
            for (int nt = 0; nt < 4; nt++)
                #pragma unroll
                for (int i = 0; i < 4; i++) {
                    int cc = (ct0 + cti) * 16 + (l >> 2) + (i >> 1) * 8;
                    int kk = n0 + nt * 8 + (l & 3) * 2 + (i & 1);
                    vbuf[kk * 130 + cc] = vacc[cti][nt][i];
                }
    }
    if (w < 8) __syncthreads();   // G1 side of the join barrier
    __syncthreads();

    float* vp = g_vpart + (size_t)(n * SPLIT + sp) * K_CL * C_DIM;
    const float* vbuf = (const float*)smb;
    #pragma unroll
    for (int r = 0; r < 16; r++) {
        int idx = tid + THREADS * r;
        vp[idx] = vbuf[(idx >> 7) * 130 + (idx & 127)];
    }
}

// ---- reduce partials, subtract a*cent, intra-normalize, partial global sums ----
__global__ void __launch_bounds__(256)
netvlad_reduce(const float* __restrict__ cent, float* __restrict__ out) {
    __shared__ float red[8];
    const int n   = blockIdx.y;
    const int kg  = blockIdx.x;
    const int tid = threadIdx.x;
    const int w   = tid >> 5, l = tid & 31;
    const int k   = kg * 8 + w;

    float as = 0.f;
    #pragma unroll
    for (int p = 0; p < SPLIT; p++) as += g_apart[(n * SPLIT + p) * K_CL + k];

    float4 v = make_float4(0.f, 0.f, 0.f, 0.f);
    #pragma unroll
    for (int p = 0; p < SPLIT; p++) {
        const float4* vp = (const float4*)(g_vpart +
            (size_t)(n * SPLIT + p) * K_CL * C_DIM + k * C_DIM);
        float4 t = vp[l];
        v.x += t.x; v.y += t.y; v.z += t.z; v.w += t.w;
    }
    float4 ct = ((const float4*)(cent + k * C_DIM))[l];
    v.x -= as * ct.x; v.y -= as * ct.y; v.z -= as * ct.z; v.w -= as * ct.w;

    float ss = v.x * v.x + v.y * v.y + v.z * v.z + v.w * v.w;
    #pragma unroll
    for (int o = 16; o; o >>= 1) ss += __shfl_xor_sync(0xffffffffu, ss, o);
    float inv = 1.f / fmaxf(sqrtf(ss), EPSV);
    v.x *= inv; v.y *= inv; v.z *= inv; v.w *= inv;
    ((float4*)(out + (size_t)n * K_CL * C_DIM + k * C_DIM))[l] = v;

    if (l == 0) red[w] = ss * inv * inv;
    __syncthreads();
    if (tid == 0) {
        float g = 0.f;
        #pragma unroll
        for (int i = 0; i < 8; i++) g += red[i];
        g_gsum[n * 8 + kg] = g;
    }
}

__global__ void __launch_bounds__(256)
netvlad_scale(float* __restrict__ out) {
    const int n   = blockIdx.x;
    const int tid = threadIdx.x;
    float g = 0.f;
    #pragma unroll
    for (int i = 0; i < 8; i++) g += g_gsum[n * 8 + i];
    const float ginv = 1.f / fmaxf(sqrtf(g), EPSV);

    float4* ob = (float4*)(out + (size_t)n * K_CL * C_DIM);
    #pragma unroll
    for (int r = 0; r < 8; r++) {
        float4 v = ob[tid + 256 * r];
        v.x *= ginv; v.y *= ginv; v.z *= ginv; v.w *= ginv;
        ob[tid + 256 * r] = v;
    }
}

extern "C" void kernel_launch(void* const* d_in, const int* in_sizes, int n_in,
                              void* d_out, int out_size) {
    const float* x     = (const float*)d_in[0];
    const float* convw = (const float*)d_in[1];
    const float* cent  = (const float*)d_in[2];
    float*       out   = (float*)d_out;

    cudaFuncSetAttribute(netvlad_main,
                         cudaFuncAttributeMaxDynamicSharedMemorySize, SMEM_BYTES);
    netvlad_main<<<dim3(SPLIT, N_IMG), THREADS, SMEM_BYTES>>>(x, convw);
    netvlad_reduce<<<dim3(8, N_IMG), 256>>>(cent, out);
    netvlad_scale<<<N_IMG, 256>>>(out);
}

// round 15
// speedup vs baseline: 2.5945x; 1.0843x over previous
#include <cuda_runtime.h>
#include <cuda_bf16.h>
#include <cstdint>
#include <math.h>

#define N_IMG   32
#define C_DIM   128
#define K_CL    64
#define S_TOT   12544
#define SC      128
#define NCHUNK  98
#define SPLIT   9
#define CPB     11
#define THREADS 512
#define EPSV    1e-12f
#define HS      64          // half-chunk pixels

#define XSTR    144         // X tile row stride bytes
#define PSTR    144
#define WSTR    272         // W row stride bytes
#define LSW     68          // Ls row stride in words

// smem byte offsets (X is hi-only bf16 now)
#define OFF_XH0 0
#define OFF_XH1 (OFF_XH0 + 128 * XSTR)      //  18432
#define OFF_WH  (OFF_XH1 + 128 * XSTR)      //  36864
#define OFF_LS0 (OFF_WH  +  64 * WSTR)      //  54272
#define OFF_LS1 (OFF_LS0 +  64 * LSW * 4)   //  71680
#define OFF_PH  (OFF_LS1 +  64 * LSW * 4)   //  89088
#define OFF_ASR (OFF_PH  +  64 * PSTR)      //  98304  (8 warps x 64 floats)
#define SMEM_BYTES (OFF_ASR + 8 * 64 * 4)   // 100352

// named barriers (0 reserved for __syncthreads)
#define BID_LSFULL 1    // +b
#define BID_LSFREE 3    // +b
#define BID_XFREE  5    // +b
#define BID_G1LOC  7
#define BID_G2LOC  8

__device__ float g_vpart[(size_t)N_IMG * SPLIT * K_CL * C_DIM];
__device__ float g_apart[N_IMG * SPLIT * K_CL];
__device__ float g_gsum[N_IMG * 8];

// ---------------- PTX helpers ----------------
__device__ __forceinline__ void bar_sync(int id, int cnt) {
    asm volatile("bar.sync %0, %1;" :: "r"(id), "r"(cnt) : "memory");
}
__device__ __forceinline__ void bar_arrive(int id, int cnt) {
    asm volatile("bar.arrive %0, %1;" :: "r"(id), "r"(cnt) : "memory");
}
__device__ __forceinline__ void ldsm4(uint32_t* r, uint32_t a) {
    asm volatile("ldmatrix.sync.aligned.m8n8.x4.shared.b16 {%0,%1,%2,%3}, [%4];"
        : "=r"(r[0]), "=r"(r[1]), "=r"(r[2]), "=r"(r[3]) : "r"(a));
}
__device__ __forceinline__ void ldsm4t(uint32_t* r, uint32_t a) {
    asm volatile("ldmatrix.sync.aligned.m8n8.x4.trans.shared.b16 {%0,%1,%2,%3}, [%4];"
        : "=r"(r[0]), "=r"(r[1]), "=r"(r[2]), "=r"(r[3]) : "r"(a));
}
__device__ __forceinline__ void mma16816(float* d, const uint32_t* a, const uint32_t* b) {
    asm volatile("mma.sync.aligned.m16n8k16.row.col.f32.bf16.bf16.f32 "
        "{%0,%1,%2,%3}, {%4,%5,%6,%7}, {%8,%9}, {%0,%1,%2,%3};"
        : "+f"(d[0]), "+f"(d[1]), "+f"(d[2]), "+f"(d[3])
        : "r"(a[0]), "r"(a[1]), "r"(a[2]), "r"(a[3]), "r"(b[0]), "r"(b[1]));
}
__device__ __forceinline__ uint32_t pack_hi(float a, float b) {
    __nv_bfloat16 ah = __float2bfloat16_rn(a);
    __nv_bfloat16 bh = __float2bfloat16_rn(b);
    return (uint32_t)__bfloat16_as_ushort(ah) | ((uint32_t)__bfloat16_as_ushort(bh) << 16);
}

__global__ void __launch_bounds__(THREADS, 1)
netvlad_main(const float* __restrict__ x, const float* __restrict__ convw) {
    extern __shared__ char smb[];
    const uint32_t sb = (uint32_t)__cvta_generic_to_shared(smb);

    const int n   = blockIdx.y;
    const int sp  = blockIdx.x;
    const int tid = threadIdx.x;
    const int w   = tid >> 5, l = tid & 31;

    // ---- W -> bf16 hi tile [k][WSTR] (all 512 threads) ----
    {
        const int k = tid >> 3, cs = (tid & 7) * 16;
        const float* wg = convw + k * C_DIM + cs;
        #pragma unroll
        for (int g = 0; g < 2; g++) {
            uint32_t hh[4];
            #pragma unroll
            for (int j = 0; j < 4; j++)
                hh[j] = pack_hi(wg[8 * g + 2 * j], wg[8 * g + 2 * j + 1]);
            *(uint4*)(smb + OFF_WH + k * WSTR + (cs + 8 * g) * 2) =
                make_uint4(hh[0], hh[1], hh[2], hh[3]);
        }
    }
    __syncthreads();

    const int chunk0 = sp * CPB;
    const int nch    = min(NCHUNK, chunk0 + CPB) - chunk0;
    const int nH     = nch * 2;
    const int sbase  = chunk0 * SC;
    const float* xb  = x + (size_t)n * C_DIM * S_TOT;

    const uint32_t XH[2] = { sb + OFF_XH0, sb + OFF_XH1 };
    const uint32_t LSO[2] = { sb + OFF_LS0, sb + OFF_LS1 };

    if (w < 8) {
        // ================= G1 group: convert X + GEMM1 =================
        const int Lc = tid >> 1;            // channel 0..127
        const int Lh = tid & 1;             // 32-pixel half
        const int mt = w >> 1, n0 = (w & 1) * 32, s0 = mt * 16;
        const uint32_t raT = ((l >> 4) & 1) * 8 + (l & 7);
        const uint32_t caT = (s0 + ((l >> 3) & 1) * 8) * 2;
        const uint32_t rbX = ((l >> 4) & 1) * 8 + (l & 7);
        const uint32_t cb16 = ((l >> 3) & 1) * 16;

        float4 ld[8];
        {
            const float* g = xb + (size_t)Lc * S_TOT + sbase + Lh * 32;
            #pragma unroll
            for (int r = 0; r < 8; r++) ld[r] = *(const float4*)(g + 4 * r);
        }

        for (int j = 0; j < nH; j++) {
            const int b = j & 1;
            if (j >= 2) bar_sync(BID_XFREE + b, 512);

            // convert & store X[b] hi (32 px per thread)
            const uint32_t xo = Lc * XSTR + Lh * 64;
            #pragma unroll
            for (int g4 = 0; g4 < 4; g4++) {
                float f[8] = { ld[2*g4].x, ld[2*g4].y, ld[2*g4].z, ld[2*g4].w,
                               ld[2*g4+1].x, ld[2*g4+1].y, ld[2*g4+1].z, ld[2*g4+1].w };
                uint32_t hh[4];
                #pragma unroll
                for (int jj2 = 0; jj2 < 4; jj2++)
                    hh[jj2] = pack_hi(f[2*jj2], f[2*jj2+1]);
                *(uint4*)(smb + (XH[b] - sb) + xo + 16 * g4) =
                    make_uint4(hh[0], hh[1], hh[2], hh[3]);
            }
            bar_sync(BID_G1LOC, 256);

            // prefetch next half-chunk
            if (j + 1 < nH) {
                const float* g = xb + (size_t)Lc * S_TOT + sbase + (j + 1) * HS + Lh * 32;
                #pragma unroll
                for (int r = 0; r < 8; r++) ld[r] = *(const float4*)(g + 4 * r);
            }

            // GEMM1: D1[s][k] = X^T W^T over c=128 (8 kq); single hi pass
            float d1[4][4];
            #pragma unroll
            for (int t = 0; t < 4; t++)
                #pragma unroll
                for (int i = 0; i < 4; i++) d1[t][i] = 0.f;

            #pragma unroll
            for (int kq = 0; kq < 8; kq++) {
                uint32_t Ah[4];
                const uint32_t ao = (kq * 16 + raT) * XSTR + caT;
                ldsm4t(Ah, XH[b] + ao);
                #pragma unroll
                for (int ntp = 0; ntp < 2; ntp++) {
                    uint32_t Bh[4];
                    const uint32_t bo = (n0 + ntp * 16 + rbX) * WSTR + kq * 32 + cb16;
                    ldsm4(Bh, sb + OFF_WH + bo);
                    mma16816(d1[2*ntp],   Ah, Bh);
                    mma16816(d1[2*ntp+1], Ah, Bh + 2);
                }
            }

            if (j >= 2) bar_sync(BID_LSFREE + b, 512);
            float* Lsb = (float*)(smb + (LSO[b] - sb));
            #pragma unroll
            for (int nt = 0; nt < 4; nt++)
                #pragma unroll
                for (int i = 0; i < 4; i++) {
                    int sr = s0 + (l >> 2) + (i >> 1) * 8;
                    int kk = n0 + nt * 8 + (l & 3) * 2 + (i & 1);
                    Lsb[sr * LSW + kk] = d1[nt][i];
                }
            bar_arrive(BID_LSFULL + b, 512);
        }
    } else {
        // ================= G2 group: softmax + GEMM2 + asum =================
        const int t2 = tid - 256;
        const int wi = w - 8;
        const int n0 = (wi & 1) * 32, ct0 = (wi >> 1) * 2;
        const int p = t2 >> 2, q = t2 & 3;
        const uint32_t raN = ((l >> 3) & 1) * 8 + (l & 7);
        const uint32_t caN = ((l >> 4) & 1) * 16;
        const uint32_t rbX = ((l >> 4) & 1) * 8 + (l & 7);
        const uint32_t cb16 = ((l >> 3) & 1) * 16;

        float vacc[2][4][4];
        #pragma unroll
        for (int c = 0; c < 2; c++)
            #pragma unroll
            for (int t = 0; t < 4; t++)
                #pragma unroll
                for (int i = 0; i < 4; i++) vacc[c][t][i] = 0.f;
        float asum_loc[16];
        #pragma unroll
        for (int jx = 0; jx < 16; jx++) asum_loc[jx] = 0.f;

        for (int jj = 0; jj < nH; jj++) {
            const int b = jj & 1;
            bar_sync(BID_LSFULL + b, 512);

            // load logits: k = q + 4*jx  (conflict-free scalar reads)
            const float* Lsb = (const float*)(smb + (LSO[b] - sb)) + p * LSW + q;
            float lg[16];
            #pragma unroll
            for (int jx = 0; jx < 16; jx++) lg[jx] = Lsb[4 * jx];
            bar_arrive(BID_LSFREE + b, 512);

            // softmax over 64 k (4 lanes per pixel, shuffle over q)
            float m = lg[0];
            #pragma unroll
            for (int jx = 1; jx < 16; jx++) m = fmaxf(m, lg[jx]);
            m = fmaxf(m, __shfl_xor_sync(0xffffffffu, m, 1));
            m = fmaxf(m, __shfl_xor_sync(0xffffffffu, m, 2));
            float ssum = 0.f;
            #pragma unroll
            for (int jx = 0; jx < 16; jx++) { lg[jx] = __expf(lg[jx] - m); ssum += lg[jx]; }
            ssum += __shfl_xor_sync(0xffffffffu, ssum, 1);
            ssum += __shfl_xor_sync(0xffffffffu, ssum, 2);
            const float inv = 1.f / ssum;

            #pragma unroll
            for (int jx = 0; jx < 16; jx++) {
                float pv = lg[jx] * inv;
                asum_loc[jx] += pv;                       // exact fp32 mass
                __nv_bfloat16 h = __float2bfloat16_rn(pv);
                const int k = q + 4 * jx;
                *(__nv_bfloat16*)(smb + OFF_PH + k * PSTR + 2 * p) = h;
            }
            bar_sync(BID_G2LOC, 256);

            // GEMM2: D2[c][k] += X P^T over s=64 (4 sq); single hi pass
            #pragma unroll
            for (int sq = 0; sq < 4; sq++) {
                uint32_t Bh[2][4];
                #pragma unroll
                for (int ntp = 0; ntp < 2; ntp++) {
                    const uint32_t bo = (n0 + ntp * 16 + rbX) * PSTR + sq * 32 + cb16;
                    ldsm4(Bh[ntp], sb + OFF_PH + bo);
                }
                #pragma unroll
                for (int cti = 0; cti < 2; cti++) {
                    uint32_t Ah[4];
                    const uint32_t ao = ((ct0 + cti) * 16 + raN) * XSTR + sq * 32 + caN;
                    ldsm4(Ah, XH[b] + ao);
                    #pragma unroll
                    for (int ntp = 0; ntp < 2; ntp++) {
                        mma16816(vacc[cti][2*ntp],   Ah, Bh[ntp]);
                        mma16816(vacc[cti][2*ntp+1], Ah, Bh[ntp] + 2);
                    }
                }
            }
            bar_arrive(BID_XFREE + b, 512);
        }

        // ---- asum end reduction: over p (in-warp shfl, cross-warp smem) ----
        {
            float* asred = (float*)(smb + OFF_ASR);
            #pragma unroll
            for (int jx = 0; jx < 16; jx++) {
                float v = asum_loc[jx];
                v += __shfl_xor_sync(0xffffffffu, v, 4);
                v += __shfl_xor_sync(0xffffffffu, v, 8);
                v += __shfl_xor_sync(0xffffffffu, v, 16);
                if (l < 4) asred[wi * 64 + l + 4 * jx] = v;
            }
            bar_sync(BID_G2LOC, 256);
            if (t2 < 64) {
                float a = 0.f;
                #pragma unroll
                for (int i = 0; i < 8; i++) a += asred[i * 64 + t2];
                g_apart[(n * SPLIT + sp) * K_CL + t2] = a;
            }
        }

        __syncthreads();   // join with G1
        // write vacc -> vbuf [k][130] (reuse X region)
        float* vbuf = (float*)smb;
        #pragma unroll
        for (int cti = 0; cti < 2; cti++)
            #pragma unroll
            for (int nt = 0; nt < 4; nt++)
                #pragma unroll
                for (int i = 0; i < 4; i++) {
                    int cc = (ct0 + cti) * 16 + (l >> 2) + (i >> 1) * 8;
                    int kk = n0 + nt * 8 + (l & 3) * 2 + (i & 1);
                    vbuf[kk * 130 + cc] = vacc[cti][nt][i];
                }
    }
    if (w < 8) __syncthreads();   // G1 side of the join barrier
    __syncthreads();

    float* vp = g_vpart + (size_t)(n * SPLIT + sp) * K_CL * C_DIM;
    const float* vbuf = (const float*)smb;
    #pragma unroll
    for (int r = 0; r < 16; r++) {
        int idx = tid + THREADS * r;
        vp[idx] = vbuf[(idx >> 7) * 130 + (idx & 127)];
    }
}

// ---- reduce partials, subtract a*cent, intra-normalize, partial global sums ----
__global__ void __launch_bounds__(256)
netvlad_reduce(const float* __restrict__ cent, float* __restrict__ out) {
    __shared__ float red[8];
    const int n   = blockIdx.y;
    const int kg  = blockIdx.x;
    const int tid = threadIdx.x;
    const int w   = tid >> 5, l = tid & 31;
    const int k   = kg * 8 + w;

    float as = 0.f;
    #pragma unroll
    for (int p = 0; p < SPLIT; p++) as += g_apart[(n * SPLIT + p) * K_CL + k];

    float4 v = make_float4(0.f, 0.f, 0.f, 0.f);
    #pragma unroll
    for (int p = 0; p < SPLIT; p++) {
        const float4* vp = (const float4*)(g_vpart +
            (size_t)(n * SPLIT + p) * K_CL * C_DIM + k * C_DIM);
        float4 t = vp[l];
        v.x += t.x; v.y += t.y; v.z += t.z; v.w += t.w;
    }
    float4 ct = ((const float4*)(cent + k * C_DIM))[l];
    v.x -= as * ct.x; v.y -= as * ct.y; v.z -= as * ct.z; v.w -= as * ct.w;

    float ss = v.x * v.x + v.y * v.y + v.z * v.z + v.w * v.w;
    #pragma unroll
    for (int o = 16; o; o >>= 1) ss += __shfl_xor_sync(0xffffffffu, ss, o);
    float inv = 1.f / fmaxf(sqrtf(ss), EPSV);
    v.x *= inv; v.y *= inv; v.z *= inv; v.w *= inv;
    ((float4*)(out + (size_t)n * K_CL * C_DIM + k * C_DIM))[l] = v;

    if (l == 0) red[w] = ss * inv * inv;
    __syncthreads();
    if (tid == 0) {
        float g = 0.f;
        #pragma unroll
        for (int i = 0; i < 8; i++) g += red[i];
        g_gsum[n * 8 + kg] = g;
    }
}

__global__ void __launch_bounds__(256)
netvlad_scale(float* __restrict__ out) {
    const int n   = blockIdx.x;
    const int tid = threadIdx.x;
    float g = 0.f;
    #pragma unroll
    for (int i = 0; i < 8; i++) g += g_gsum[n * 8 + i];
    const float ginv = 1.f / fmaxf(sqrtf(g), EPSV);

    float4* ob = (float4*)(out + (size_t)n * K_CL * C_DIM);
    #pragma unroll
    for (int r = 0; r < 8; r++) {
        float4 v = ob[tid + 256 * r];
        v.x *= ginv; v.y *= ginv; v.z *= ginv; v.w *= ginv;
        ob[tid + 256 * r] = v;
    }
}

extern "C" void kernel_launch(void* const* d_in, const int* in_sizes, int n_in,
                              void* d_out, int out_size) {
    const float* x     = (const float*)d_in[0];
    const float* convw = (const float*)d_in[1];
    const float* cent  = (const float*)d_in[2];
    float*       out   = (float*)d_out;

    cudaFuncSetAttribute(netvlad_main,
                         cudaFuncAttributeMaxDynamicSharedMemorySize, SMEM_BYTES);
    netvlad_main<<<dim3(SPLIT, N_IMG), THREADS, SMEM_BYTES>>>(x, convw);
    netvlad_reduce<<<dim3(8, N_IMG), 256>>>(cent, out);
    netvlad_scale<<<N_IMG, 256>>>(out);
}